// round 15
// baseline (speedup 1.0000x reference)
#include <cuda_runtime.h>
#include <cuda_fp16.h>
#include <cstdint>

// Problem dims
#define MDIM 8192
#define NDIM 4096
#define KDIM 4096

// GEMM tiling — fp16 mma.sync path (tcgen05 unavailable: harness compiles via
// generic compute_103 which gates off the 'a'-suffix accelerated features).
// 128x128 CTA tile, BK=64, 3 stages, 2 CTAs/SM — R11/R14 config (empirical
// optimum; 512-thr CTA and register-rotation both regressed against it).
#define BM 128
#define BN 128
#define BK 64
#define KCH (KDIM / BK)                 // 64
#define STAGES 3
#define ASTAGE (BM * 128)               // 16 KB
#define BSTAGE (BN * 128)               // 16 KB
#define STG_BYTES (ASTAGE + BSTAGE)     // 32 KB
#define SMEM_BYTES (STAGES * STG_BYTES) // 96 KB -> 2 CTAs/SM

// Scratch: fp16 preprocessed weight + fp16-rounded X.
__device__ __half g_wh[(size_t)NDIM * (size_t)KDIM];   // 32 MB
__device__ __half g_xh[(size_t)MDIM * (size_t)KDIM];   // 64 MB

// ---------------------------------------------------------------- helpers
__device__ __forceinline__ uint32_t smem_u32(const void* p) {
    uint32_t a;
    asm("{ .reg .u64 t; cvta.to.shared.u64 t, %1; cvt.u32.u64 %0, t; }"
        : "=r"(a) : "l"(p));
    return a;
}

__device__ __forceinline__ void cp16(uint32_t dst, const void* src) {
    asm volatile("cp.async.cg.shared.global [%0], [%1], 16;" :: "r"(dst), "l"(src));
}

__device__ __forceinline__ void ldsm4(uint32_t* r, uint32_t addr) {
    asm volatile("ldmatrix.sync.aligned.m8n8.x4.shared.b16 {%0,%1,%2,%3}, [%4];"
                 : "=r"(r[0]), "=r"(r[1]), "=r"(r[2]), "=r"(r[3]) : "r"(addr));
}

__device__ __forceinline__ void mma_f16(float* d, const uint32_t* a, const uint32_t* b) {
    asm volatile(
        "mma.sync.aligned.m16n8k16.row.col.f32.f16.f16.f32 "
        "{%0,%1,%2,%3}, {%4,%5,%6,%7}, {%8,%9}, {%0,%1,%2,%3};"
        : "+f"(d[0]), "+f"(d[1]), "+f"(d[2]), "+f"(d[3])
        : "r"(a[0]), "r"(a[1]), "r"(a[2]), "r"(a[3]), "r"(b[0]), "r"(b[1]));
}

// --------------------------------------------- fused preprocess kernel
// Blocks [0, NDIM): one block per weight row, register-resident (16 weights =
//   2 outlier windows per thread): mean-center, sign*mean|.|, restore
//   per-8-window argmax-|w| element, round fp16 (RN) -> g_wh.
// Blocks [NDIM, ...): X fp32 -> fp16 (RN) -> g_xh (pure DRAM streaming).
__global__ __launch_bounds__(256, 1) void prep_all_kernel(const float* __restrict__ W,
                                                          const float* __restrict__ X) {
    __shared__ float sred[8];
    const int tid = threadIdx.x;

    if (blockIdx.x >= NDIM) {
        const size_t i = (size_t)(blockIdx.x - NDIM) * 256 + tid;   // 8-elt group
        float4 v0 = reinterpret_cast<const float4*>(X)[i * 2 + 0];
        float4 v1 = reinterpret_cast<const float4*>(X)[i * 2 + 1];
        __half o8[8];
        o8[0] = __float2half_rn(v0.x); o8[1] = __float2half_rn(v0.y);
        o8[2] = __float2half_rn(v0.z); o8[3] = __float2half_rn(v0.w);
        o8[4] = __float2half_rn(v1.x); o8[5] = __float2half_rn(v1.y);
        o8[6] = __float2half_rn(v1.z); o8[7] = __float2half_rn(v1.w);
        reinterpret_cast<uint4*>(g_xh)[i] = *reinterpret_cast<const uint4*>(o8);
        return;
    }

    const int row = blockIdx.x;
    const float* wr = W + (size_t)row * KDIM + tid * 16;

    float v[16];
    #pragma unroll
    for (int q = 0; q < 4; q++) {
        float4 t = *reinterpret_cast<const float4*>(wr + q * 4);
        v[q * 4 + 0] = t.x; v[q * 4 + 1] = t.y;
        v[q * 4 + 2] = t.z; v[q * 4 + 3] = t.w;
    }

    float a = 0.f;
    #pragma unroll
    for (int j = 0; j < 16; j++) a += v[j];
    #pragma unroll
    for (int o = 16; o; o >>= 1) a += __shfl_xor_sync(0xffffffffu, a, o);
    if ((tid & 31) == 0) sred[tid >> 5] = a;
    __syncthreads();
    if (tid == 0) {
        float t = 0.f;
        for (int j = 0; j < 8; j++) t += sred[j];
        sred[0] = t * (1.0f / KDIM);
    }
    __syncthreads();
    const float mu = sred[0];
    __syncthreads();

    float b = 0.f;
    #pragma unroll
    for (int j = 0; j < 16; j++) b += fabsf(v[j] - mu);
    #pragma unroll
    for (int o = 16; o; o >>= 1) b += __shfl_xor_sync(0xffffffffu, b, o);
    if ((tid & 31) == 0) sred[tid >> 5] = b;
    __syncthreads();
    if (tid == 0) {
        float t = 0.f;
        for (int j = 0; j < 8; j++) t += sred[j];
        sred[0] = t * (1.0f / KDIM);
    }
    __syncthreads();
    const float scale = sred[0];

    __half o16[16];
    #pragma unroll
    for (int w8 = 0; w8 < 2; w8++) {
        const float* vw = v + w8 * 8;
        int best = 0;
        float bv = fabsf(vw[0]);
        #pragma unroll
        for (int j = 1; j < 8; j++) {
            float av = fabsf(vw[j]);
            if (av > bv) { bv = av; best = j; }   // strict > == first argmax
        }
        #pragma unroll
        for (int j = 0; j < 8; j++) {
            float wc = vw[j] - mu;
            float q = (wc > 0.f) ? scale : ((wc < 0.f) ? -scale : 0.f);
            if (j == best) q = vw[j];
            o16[w8 * 8 + j] = __float2half_rn(q);
        }
    }
    __half* outr = g_wh + (size_t)row * KDIM + tid * 16;
    *reinterpret_cast<uint4*>(outr)     = *reinterpret_cast<const uint4*>(o16);
    *reinterpret_cast<uint4*>(outr + 8) = *reinterpret_cast<const uint4*>(o16 + 8);
}

// ---------------------------------------------------------- fp16 GEMM kernel
// out[m,n] = sum_k g_xh[m,k] * g_wh[n,k] + bias[n]
// 128x128 CTA tile, BK=64, 3-stage cp.async, 2 CTAs/SM, mma.sync.m16n8k16.
// Single-variable change vs R14: ks=0 fragment loads are issued immediately
// after the barrier (before the cp.async prefetch block), with fresh registers
// everywhere (no rotation — that was R12's regression).
__global__ __launch_bounds__(256, 2) void gemm_kernel(const float* __restrict__ bias,
                                                      float* __restrict__ out) {
    extern __shared__ __align__(1024) char smem[];
    const uint32_t sbase = smem_u32(smem);
    const int tid = threadIdx.x;
    const int lane = tid & 31;
    const int wid = tid >> 5;
    const int wm = wid & 1;          // 2 warps along M (64 rows each)
    const int wn = wid >> 1;         // 4 warps along N (32 cols each)

    const int m0 = blockIdx.y * BM;
    const int n0 = blockIdx.x * BN;
    const __half* Xb = g_xh + (size_t)m0 * KDIM;
    const __half* Wb = g_wh + (size_t)n0 * KDIM;

    // ---- cp.async per-thread constants (16B = 8 halves per chunk) ----
    const int kb    = tid & 7;            // 16B chunk within 128B row
    const int rbase = tid >> 3;           // base row (+= 32 per iteration)
    const uint32_t dA0 = (uint32_t)rbase * 128 + (uint32_t)((kb ^ (rbase & 7)) << 4);
    const uint32_t dB0 = ASTAGE + dA0;
    const __half* srcA0 = Xb + (size_t)rbase * KDIM + kb * 8;
    const __half* srcB0 = Wb + (size_t)rbase * KDIM + kb * 8;

    // ---- ldmatrix per-lane constants ----
    const int e7 = lane & 7;
    const int tA = lane >> 4;             // A: k-chunk select bit
    const int tB = (lane >> 3) & 1;       // B: k-chunk select bit
    uint32_t aoff[4], boff[2];
    #pragma unroll
    for (int mt = 0; mt < 4; mt++) {
        // A 16x16 tile: lanes 0-15 -> rows 0-15 (k 0-7), lanes 16-31 -> k 8-15
        const int rowAf = wm * 64 + mt * 16 + (lane & 15);
        aoff[mt] = (uint32_t)rowAf * 128;
    }
    #pragma unroll
    for (int ntp = 0; ntp < 2; ntp++) {
        // B 16(n)x16(k) tile: lanes {0-7,8-15} -> n 0-7 (k 0-7, 8-15),
        //                     lanes {16-23,24-31} -> n 8-15
        const int rowBf = wn * 32 + ntp * 16 + e7 + ((lane >> 4) & 1) * 8;
        boff[ntp] = ASTAGE + (uint32_t)rowBf * 128;
    }

    float acc[4][4][4];
    #pragma unroll
    for (int mt = 0; mt < 4; mt++)
        #pragma unroll
        for (int nt = 0; nt < 4; nt++)
            #pragma unroll
            for (int q = 0; q < 4; q++) acc[mt][nt][q] = 0.f;

    // ---- prologue: fill STAGES-1 stages ----
    #pragma unroll
    for (int s = 0; s < STAGES - 1; s++) {
        const uint32_t stg = sbase + s * STG_BYTES;
        #pragma unroll
        for (int i = 0; i < 4; i++)
            cp16(stg + dA0 + i * 4096, srcA0 + (size_t)i * 32 * KDIM + s * BK);
        #pragma unroll
        for (int i = 0; i < 4; i++)
            cp16(stg + dB0 + i * 4096, srcB0 + (size_t)i * 32 * KDIM + s * BK);
        asm volatile("cp.async.commit_group;" ::: "memory");
    }

    // ---- main loop (one barrier per chunk; ring of 3 stages) ----
    int sc = 0;               // compute stage
    int sl = STAGES - 1;      // load stage for chunk c+STAGES-1
    for (int c = 0; c < KCH; c++) {
        asm volatile("cp.async.wait_group %0;" :: "n"(STAGES - 2) : "memory");
        __syncthreads();

        const uint32_t stg = sbase + sc * STG_BYTES;

        // ks=0 fragment loads FIRST (fresh regs) — start LDS latency now
        uint32_t af0[4][4], bf0[2][4];
        {
            const uint32_t cA = (uint32_t)((tA ^ e7) << 4);
            const uint32_t cB = (uint32_t)((tB ^ e7) << 4);
            #pragma unroll
            for (int mt = 0; mt < 4; mt++) ldsm4(af0[mt], stg + aoff[mt] + cA);
            #pragma unroll
            for (int ntp = 0; ntp < 2; ntp++) ldsm4(bf0[ntp], stg + boff[ntp] + cB);
        }

        // prefetch chunk c+STAGES-1 (issue slots overlap the LDSM shadow)
        const int cn = c + STAGES - 1;
        if (cn < KCH) {
            const uint32_t stgl = sbase + sl * STG_BYTES;
            #pragma unroll
            for (int i = 0; i < 4; i++)
                cp16(stgl + dA0 + i * 4096, srcA0 + (size_t)i * 32 * KDIM + cn * BK);
            #pragma unroll
            for (int i = 0; i < 4; i++)
                cp16(stgl + dB0 + i * 4096, srcB0 + (size_t)i * 32 * KDIM + cn * BK);
        }
        asm volatile("cp.async.commit_group;" ::: "memory");

        // ks=0 compute
        #pragma unroll
        for (int mt = 0; mt < 4; mt++)
            #pragma unroll
            for (int ntp = 0; ntp < 2; ntp++) {
                mma_f16(acc[mt][ntp * 2 + 0], af0[mt], &bf0[ntp][0]);
                mma_f16(acc[mt][ntp * 2 + 1], af0[mt], &bf0[ntp][2]);
            }

        // ks=1..3: fresh regs per iteration (ptxas renames + pipelines)
        #pragma unroll
        for (int ks = 1; ks < 4; ks++) {
            uint32_t af[4][4], bf[2][4];
            const uint32_t cA = (uint32_t)((((ks << 1) + tA) ^ e7) << 4);
            const uint32_t cB = (uint32_t)((((ks << 1) + tB) ^ e7) << 4);
            #pragma unroll
            for (int mt = 0; mt < 4; mt++) ldsm4(af[mt], stg + aoff[mt] + cA);
            #pragma unroll
            for (int ntp = 0; ntp < 2; ntp++) ldsm4(bf[ntp], stg + boff[ntp] + cB);
            #pragma unroll
            for (int mt = 0; mt < 4; mt++)
                #pragma unroll
                for (int ntp = 0; ntp < 2; ntp++) {
                    mma_f16(acc[mt][ntp * 2 + 0], af[mt], &bf[ntp][0]);
                    mma_f16(acc[mt][ntp * 2 + 1], af[mt], &bf[ntp][2]);
                }
        }
        sc = (sc + 1 == STAGES) ? 0 : sc + 1;
        sl = (sl + 1 == STAGES) ? 0 : sl + 1;
    }

    // ---- epilogue: bias add + store ----
    const int g = lane >> 2;
    const int tg = lane & 3;
    float2 bv[4];
    #pragma unroll
    for (int nt = 0; nt < 4; nt++)
        bv[nt] = *reinterpret_cast<const float2*>(bias + n0 + wn * 32 + nt * 8 + tg * 2);

    #pragma unroll
    for (int mt = 0; mt < 4; mt++) {
        const int row = m0 + wm * 64 + mt * 16 + g;
        float* o0 = out + (size_t)row * NDIM + n0 + wn * 32;
        float* o1 = o0 + 8 * NDIM;   // row + 8
        #pragma unroll
        for (int nt = 0; nt < 4; nt++) {
            const int col = nt * 8 + tg * 2;
            float2 v0, v1;
            v0.x = acc[mt][nt][0] + bv[nt].x;
            v0.y = acc[mt][nt][1] + bv[nt].y;
            v1.x = acc[mt][nt][2] + bv[nt].x;
            v1.y = acc[mt][nt][3] + bv[nt].y;
            *reinterpret_cast<float2*>(o0 + col) = v0;
            *reinterpret_cast<float2*>(o1 + col) = v1;
        }
    }
}

// ------------------------------------------------------------------ launch
extern "C" void kernel_launch(void* const* d_in, const int* in_sizes, int n_in,
                              void* d_out, int out_size) {
    (void)in_sizes; (void)n_in; (void)out_size;
    const float* X = (const float*)d_in[0];     // [4,2048,4096] -> [8192,4096]
    const float* W = (const float*)d_in[1];     // [4096,4096]
    const float* B = (const float*)d_in[2];     // [4096]
    float* O = (float*)d_out;                   // [8192,4096]

    const int conv_blocks = (MDIM * KDIM / 8) / 256;          // 16384
    prep_all_kernel<<<NDIM + conv_blocks, 256>>>(W, X);       // fused pre-pass

    cudaFuncSetAttribute(gemm_kernel, cudaFuncAttributeMaxDynamicSharedMemorySize, SMEM_BYTES);
    dim3 grid(NDIM / BN, MDIM / BM);            // (32, 64)
    gemm_kernel<<<grid, 256, SMEM_BYTES>>>(B, O);
}

// round 16
// speedup vs baseline: 1.0461x; 1.0461x over previous
#include <cuda_runtime.h>
#include <cuda_fp16.h>
#include <cstdint>

// Problem dims
#define MDIM 8192
#define NDIM 4096
#define KDIM 4096

// GEMM tiling — fp16 mma.sync path (tcgen05 unavailable: harness compiles via
// generic compute_103 which gates off the 'a'-suffix accelerated features).
// 128x128 CTA tile, BK=64, 3 stages, 2 CTAs/SM — R14 config, FROZEN: every
// loop-body deviation (register rotation R12, 512-thr CTA R13, ks=0 hoist R15)
// regressed. ptxas pipelines the uniform 4-iteration ks loop best.
#define BM 128
#define BN 128
#define BK 64
#define KCH (KDIM / BK)                 // 64
#define STAGES 3
#define ASTAGE (BM * 128)               // 16 KB
#define BSTAGE (BN * 128)               // 16 KB
#define STG_BYTES (ASTAGE + BSTAGE)     // 32 KB
#define SMEM_BYTES (STAGES * STG_BYTES) // 96 KB -> 2 CTAs/SM

// Scratch: fp16 preprocessed weight + fp16-rounded X.
__device__ __half g_wh[(size_t)NDIM * (size_t)KDIM];   // 32 MB
__device__ __half g_xh[(size_t)MDIM * (size_t)KDIM];   // 64 MB

// ---------------------------------------------------------------- helpers
__device__ __forceinline__ uint32_t smem_u32(const void* p) {
    uint32_t a;
    asm("{ .reg .u64 t; cvta.to.shared.u64 t, %1; cvt.u32.u64 %0, t; }"
        : "=r"(a) : "l"(p));
    return a;
}

__device__ __forceinline__ void cp16(uint32_t dst, const void* src) {
    asm volatile("cp.async.cg.shared.global [%0], [%1], 16;" :: "r"(dst), "l"(src));
}

__device__ __forceinline__ void ldsm4(uint32_t* r, uint32_t addr) {
    asm volatile("ldmatrix.sync.aligned.m8n8.x4.shared.b16 {%0,%1,%2,%3}, [%4];"
                 : "=r"(r[0]), "=r"(r[1]), "=r"(r[2]), "=r"(r[3]) : "r"(addr));
}

__device__ __forceinline__ void mma_f16(float* d, const uint32_t* a, const uint32_t* b) {
    asm volatile(
        "mma.sync.aligned.m16n8k16.row.col.f32.f16.f16.f32 "
        "{%0,%1,%2,%3}, {%4,%5,%6,%7}, {%8,%9}, {%0,%1,%2,%3};"
        : "+f"(d[0]), "+f"(d[1]), "+f"(d[2]), "+f"(d[3])
        : "r"(a[0]), "r"(a[1]), "r"(a[2]), "r"(a[3]), "r"(b[0]), "r"(b[1]));
}

// --------------------------------------------- fused preprocess kernel
// Blocks [0, NDIM): one block per weight row, register-resident (16 weights =
//   2 outlier windows per thread): mean-center, sign*mean|.|, restore
//   per-8-window argmax-|w| element, round fp16 (RN) -> g_wh.
// Blocks [NDIM, ...): X fp32 -> fp16 (RN), 16 elements/thread (2 independent
//   uint4 loads raise MLP; the convert arm ran at only 78% DRAM with 8/thread).
__global__ __launch_bounds__(256, 1) void prep_all_kernel(const float* __restrict__ W,
                                                          const float* __restrict__ X) {
    __shared__ float sred[8];
    const int tid = threadIdx.x;

    if (blockIdx.x >= NDIM) {
        // ---- X conversion: 16 elements per thread ----
        const size_t i = ((size_t)(blockIdx.x - NDIM) * 256 + tid) * 2; // uint4-out idx
        float4 v0 = reinterpret_cast<const float4*>(X)[i * 2 + 0];
        float4 v1 = reinterpret_cast<const float4*>(X)[i * 2 + 1];
        float4 v2 = reinterpret_cast<const float4*>(X)[i * 2 + 2];
        float4 v3 = reinterpret_cast<const float4*>(X)[i * 2 + 3];
        __half o16[16];
        o16[0]  = __float2half_rn(v0.x); o16[1]  = __float2half_rn(v0.y);
        o16[2]  = __float2half_rn(v0.z); o16[3]  = __float2half_rn(v0.w);
        o16[4]  = __float2half_rn(v1.x); o16[5]  = __float2half_rn(v1.y);
        o16[6]  = __float2half_rn(v1.z); o16[7]  = __float2half_rn(v1.w);
        o16[8]  = __float2half_rn(v2.x); o16[9]  = __float2half_rn(v2.y);
        o16[10] = __float2half_rn(v2.z); o16[11] = __float2half_rn(v2.w);
        o16[12] = __float2half_rn(v3.x); o16[13] = __float2half_rn(v3.y);
        o16[14] = __float2half_rn(v3.z); o16[15] = __float2half_rn(v3.w);
        reinterpret_cast<uint4*>(g_xh)[i + 0] = *reinterpret_cast<const uint4*>(o16);
        reinterpret_cast<uint4*>(g_xh)[i + 1] = *reinterpret_cast<const uint4*>(o16 + 8);
        return;
    }

    const int row = blockIdx.x;
    const float* wr = W + (size_t)row * KDIM + tid * 16;

    float v[16];
    #pragma unroll
    for (int q = 0; q < 4; q++) {
        float4 t = *reinterpret_cast<const float4*>(wr + q * 4);
        v[q * 4 + 0] = t.x; v[q * 4 + 1] = t.y;
        v[q * 4 + 2] = t.z; v[q * 4 + 3] = t.w;
    }

    float a = 0.f;
    #pragma unroll
    for (int j = 0; j < 16; j++) a += v[j];
    #pragma unroll
    for (int o = 16; o; o >>= 1) a += __shfl_xor_sync(0xffffffffu, a, o);
    if ((tid & 31) == 0) sred[tid >> 5] = a;
    __syncthreads();
    if (tid == 0) {
        float t = 0.f;
        for (int j = 0; j < 8; j++) t += sred[j];
        sred[0] = t * (1.0f / KDIM);
    }
    __syncthreads();
    const float mu = sred[0];
    __syncthreads();

    float b = 0.f;
    #pragma unroll
    for (int j = 0; j < 16; j++) b += fabsf(v[j] - mu);
    #pragma unroll
    for (int o = 16; o; o >>= 1) b += __shfl_xor_sync(0xffffffffu, b, o);
    if ((tid & 31) == 0) sred[tid >> 5] = b;
    __syncthreads();
    if (tid == 0) {
        float t = 0.f;
        for (int j = 0; j < 8; j++) t += sred[j];
        sred[0] = t * (1.0f / KDIM);
    }
    __syncthreads();
    const float scale = sred[0];

    __half o16[16];
    #pragma unroll
    for (int w8 = 0; w8 < 2; w8++) {
        const float* vw = v + w8 * 8;
        int best = 0;
        float bv = fabsf(vw[0]);
        #pragma unroll
        for (int j = 1; j < 8; j++) {
            float av = fabsf(vw[j]);
            if (av > bv) { bv = av; best = j; }   // strict > == first argmax
        }
        #pragma unroll
        for (int j = 0; j < 8; j++) {
            float wc = vw[j] - mu;
            float q = (wc > 0.f) ? scale : ((wc < 0.f) ? -scale : 0.f);
            if (j == best) q = vw[j];
            o16[w8 * 8 + j] = __float2half_rn(q);
        }
    }
    __half* outr = g_wh + (size_t)row * KDIM + tid * 16;
    *reinterpret_cast<uint4*>(outr)     = *reinterpret_cast<const uint4*>(o16);
    *reinterpret_cast<uint4*>(outr + 8) = *reinterpret_cast<const uint4*>(o16 + 8);
}

// ---------------------------------------------------------- fp16 GEMM kernel
// out[m,n] = sum_k g_xh[m,k] * g_wh[n,k] + bias[n]
// 128x128 CTA tile, BK=64, 3-stage cp.async, 2 CTAs/SM, mma.sync.m16n8k16.
// EXACT R14 loop body (uniform 4-iteration ks loop, batched ldsm, fresh
// per-iteration registers) — frozen after R12/R13/R15 all regressed.
__global__ __launch_bounds__(256, 2) void gemm_kernel(const float* __restrict__ bias,
                                                      float* __restrict__ out) {
    extern __shared__ __align__(1024) char smem[];
    const uint32_t sbase = smem_u32(smem);
    const int tid = threadIdx.x;
    const int lane = tid & 31;
    const int wid = tid >> 5;
    const int wm = wid & 1;          // 2 warps along M (64 rows each)
    const int wn = wid >> 1;         // 4 warps along N (32 cols each)

    const int m0 = blockIdx.y * BM;
    const int n0 = blockIdx.x * BN;
    const __half* Xb = g_xh + (size_t)m0 * KDIM;
    const __half* Wb = g_wh + (size_t)n0 * KDIM;

    // ---- cp.async per-thread constants (16B = 8 halves per chunk) ----
    const int kb    = tid & 7;            // 16B chunk within 128B row
    const int rbase = tid >> 3;           // base row (+= 32 per iteration)
    const uint32_t dA0 = (uint32_t)rbase * 128 + (uint32_t)((kb ^ (rbase & 7)) << 4);
    const uint32_t dB0 = ASTAGE + dA0;
    const __half* srcA0 = Xb + (size_t)rbase * KDIM + kb * 8;
    const __half* srcB0 = Wb + (size_t)rbase * KDIM + kb * 8;

    // ---- ldmatrix per-lane constants ----
    const int e7 = lane & 7;
    const int tA = lane >> 4;             // A: k-chunk select bit
    const int tB = (lane >> 3) & 1;       // B: k-chunk select bit
    uint32_t aoff[4], boff[2];
    #pragma unroll
    for (int mt = 0; mt < 4; mt++) {
        // A 16x16 tile: lanes 0-15 -> rows 0-15 (k 0-7), lanes 16-31 -> k 8-15
        const int rowAf = wm * 64 + mt * 16 + (lane & 15);
        aoff[mt] = (uint32_t)rowAf * 128;
    }
    #pragma unroll
    for (int ntp = 0; ntp < 2; ntp++) {
        // B 16(n)x16(k) tile: lanes {0-7,8-15} -> n 0-7 (k 0-7, 8-15),
        //                     lanes {16-23,24-31} -> n 8-15
        const int rowBf = wn * 32 + ntp * 16 + e7 + ((lane >> 4) & 1) * 8;
        boff[ntp] = ASTAGE + (uint32_t)rowBf * 128;
    }

    float acc[4][4][4];
    #pragma unroll
    for (int mt = 0; mt < 4; mt++)
        #pragma unroll
        for (int nt = 0; nt < 4; nt++)
            #pragma unroll
            for (int q = 0; q < 4; q++) acc[mt][nt][q] = 0.f;

    // ---- prologue: fill STAGES-1 stages ----
    #pragma unroll
    for (int s = 0; s < STAGES - 1; s++) {
        const uint32_t stg = sbase + s * STG_BYTES;
        #pragma unroll
        for (int i = 0; i < 4; i++)
            cp16(stg + dA0 + i * 4096, srcA0 + (size_t)i * 32 * KDIM + s * BK);
        #pragma unroll
        for (int i = 0; i < 4; i++)
            cp16(stg + dB0 + i * 4096, srcB0 + (size_t)i * 32 * KDIM + s * BK);
        asm volatile("cp.async.commit_group;" ::: "memory");
    }

    // ---- main loop (one barrier per chunk; ring of 3 stages) ----
    int sc = 0;               // compute stage
    int sl = STAGES - 1;      // load stage for chunk c+STAGES-1
    for (int c = 0; c < KCH; c++) {
        asm volatile("cp.async.wait_group %0;" :: "n"(STAGES - 2) : "memory");
        __syncthreads();

        const int cn = c + STAGES - 1;
        if (cn < KCH) {
            const uint32_t stg = sbase + sl * STG_BYTES;
            #pragma unroll
            for (int i = 0; i < 4; i++)
                cp16(stg + dA0 + i * 4096, srcA0 + (size_t)i * 32 * KDIM + cn * BK);
            #pragma unroll
            for (int i = 0; i < 4; i++)
                cp16(stg + dB0 + i * 4096, srcB0 + (size_t)i * 32 * KDIM + cn * BK);
        }
        asm volatile("cp.async.commit_group;" ::: "memory");

        // compute chunk c: 4 k16 steps (fresh regs each ks — ptxas pipelines)
        const uint32_t stg = sbase + sc * STG_BYTES;
        #pragma unroll
        for (int ks = 0; ks < 4; ks++) {
            uint32_t af[4][4], bf[2][4];
            const uint32_t cA = (uint32_t)((((ks << 1) + tA) ^ e7) << 4);
            const uint32_t cB = (uint32_t)((((ks << 1) + tB) ^ e7) << 4);
            #pragma unroll
            for (int mt = 0; mt < 4; mt++) ldsm4(af[mt], stg + aoff[mt] + cA);
            #pragma unroll
            for (int ntp = 0; ntp < 2; ntp++) ldsm4(bf[ntp], stg + boff[ntp] + cB);
            #pragma unroll
            for (int mt = 0; mt < 4; mt++)
                #pragma unroll
                for (int ntp = 0; ntp < 2; ntp++) {
                    mma_f16(acc[mt][ntp * 2 + 0], af[mt], &bf[ntp][0]);
                    mma_f16(acc[mt][ntp * 2 + 1], af[mt], &bf[ntp][2]);
                }
        }
        sc = (sc + 1 == STAGES) ? 0 : sc + 1;
        sl = (sl + 1 == STAGES) ? 0 : sl + 1;
    }

    // ---- epilogue: bias add + store ----
    const int g = lane >> 2;
    const int tg = lane & 3;
    float2 bv[4];
    #pragma unroll
    for (int nt = 0; nt < 4; nt++)
        bv[nt] = *reinterpret_cast<const float2*>(bias + n0 + wn * 32 + nt * 8 + tg * 2);

    #pragma unroll
    for (int mt = 0; mt < 4; mt++) {
        const int row = m0 + wm * 64 + mt * 16 + g;
        float* o0 = out + (size_t)row * NDIM + n0 + wn * 32;
        float* o1 = o0 + 8 * NDIM;   // row + 8
        #pragma unroll
        for (int nt = 0; nt < 4; nt++) {
            const int col = nt * 8 + tg * 2;
            float2 v0, v1;
            v0.x = acc[mt][nt][0] + bv[nt].x;
            v0.y = acc[mt][nt][1] + bv[nt].y;
            v1.x = acc[mt][nt][2] + bv[nt].x;
            v1.y = acc[mt][nt][3] + bv[nt].y;
            *reinterpret_cast<float2*>(o0 + col) = v0;
            *reinterpret_cast<float2*>(o1 + col) = v1;
        }
    }
}

// ------------------------------------------------------------------ launch
extern "C" void kernel_launch(void* const* d_in, const int* in_sizes, int n_in,
                              void* d_out, int out_size) {
    (void)in_sizes; (void)n_in; (void)out_size;
    const float* X = (const float*)d_in[0];     // [4,2048,4096] -> [8192,4096]
    const float* W = (const float*)d_in[1];     // [4096,4096]
    const float* B = (const float*)d_in[2];     // [4096]
    float* O = (float*)d_out;                   // [8192,4096]

    const int conv_blocks = (MDIM * KDIM / 16) / 256;         // 8192
    prep_all_kernel<<<NDIM + conv_blocks, 256>>>(W, X);       // fused pre-pass

    cudaFuncSetAttribute(gemm_kernel, cudaFuncAttributeMaxDynamicSharedMemorySize, SMEM_BYTES);
    dim3 grid(NDIM / BN, MDIM / BM);            // (32, 64)
    gemm_kernel<<<grid, 256, SMEM_BYTES>>>(B, O);
}

// round 17
// speedup vs baseline: 1.1160x; 1.0668x over previous
#include <cuda_runtime.h>
#include <cuda_fp16.h>
#include <cstdint>

// Problem dims
#define MDIM 8192
#define NDIM 4096
#define KDIM 4096

// GEMM tiling — fp16 mma.sync path (tcgen05 unavailable: harness compiles via
// generic compute_103 which gates off the 'a'-suffix accelerated features).
// 128x128 CTA tile, BK=64, 3 stages, 2 CTAs/SM — R14 config. The per-chunk
// body is FROZEN (R12/R13/R15 all regressed); this round only unrolls the
// main loop by the stage period (3) so stage indices are compile-time.
#define BM 128
#define BN 128
#define BK 64
#define KCH (KDIM / BK)                 // 64
#define STAGES 3
#define ASTAGE (BM * 128)               // 16 KB
#define BSTAGE (BN * 128)               // 16 KB
#define STG_BYTES (ASTAGE + BSTAGE)     // 32 KB
#define SMEM_BYTES (STAGES * STG_BYTES) // 96 KB -> 2 CTAs/SM

// Scratch: fp16 preprocessed weight + fp16-rounded X.
__device__ __half g_wh[(size_t)NDIM * (size_t)KDIM];   // 32 MB
__device__ __half g_xh[(size_t)MDIM * (size_t)KDIM];   // 64 MB

// ---------------------------------------------------------------- helpers
__device__ __forceinline__ uint32_t smem_u32(const void* p) {
    uint32_t a;
    asm("{ .reg .u64 t; cvta.to.shared.u64 t, %1; cvt.u32.u64 %0, t; }"
        : "=r"(a) : "l"(p));
    return a;
}

__device__ __forceinline__ void cp16(uint32_t dst, const void* src) {
    asm volatile("cp.async.cg.shared.global [%0], [%1], 16;" :: "r"(dst), "l"(src));
}

__device__ __forceinline__ void ldsm4(uint32_t* r, uint32_t addr) {
    asm volatile("ldmatrix.sync.aligned.m8n8.x4.shared.b16 {%0,%1,%2,%3}, [%4];"
                 : "=r"(r[0]), "=r"(r[1]), "=r"(r[2]), "=r"(r[3]) : "r"(addr));
}

__device__ __forceinline__ void mma_f16(float* d, const uint32_t* a, const uint32_t* b) {
    asm volatile(
        "mma.sync.aligned.m16n8k16.row.col.f32.f16.f16.f32 "
        "{%0,%1,%2,%3}, {%4,%5,%6,%7}, {%8,%9}, {%0,%1,%2,%3};"
        : "+f"(d[0]), "+f"(d[1]), "+f"(d[2]), "+f"(d[3])
        : "r"(a[0]), "r"(a[1]), "r"(a[2]), "r"(a[3]), "r"(b[0]), "r"(b[1]));
}

// --------------------------------------------- fused preprocess kernel
// Blocks [0, NDIM): one block per weight row, register-resident (16 weights =
//   2 outlier windows per thread): mean-center, sign*mean|.|, restore
//   per-8-window argmax-|w| element, round fp16 (RN) -> g_wh.
// Blocks [NDIM, ...): X fp32 -> fp16 (RN), 8 elements/thread (R14 measured
//   best; the 16/thread variant was neutral).
__global__ __launch_bounds__(256, 1) void prep_all_kernel(const float* __restrict__ W,
                                                          const float* __restrict__ X) {
    __shared__ float sred[8];
    const int tid = threadIdx.x;

    if (blockIdx.x >= NDIM) {
        const size_t i = (size_t)(blockIdx.x - NDIM) * 256 + tid;   // 8-elt group
        float4 v0 = reinterpret_cast<const float4*>(X)[i * 2 + 0];
        float4 v1 = reinterpret_cast<const float4*>(X)[i * 2 + 1];
        __half o8[8];
        o8[0] = __float2half_rn(v0.x); o8[1] = __float2half_rn(v0.y);
        o8[2] = __float2half_rn(v0.z); o8[3] = __float2half_rn(v0.w);
        o8[4] = __float2half_rn(v1.x); o8[5] = __float2half_rn(v1.y);
        o8[6] = __float2half_rn(v1.z); o8[7] = __float2half_rn(v1.w);
        reinterpret_cast<uint4*>(g_xh)[i] = *reinterpret_cast<const uint4*>(o8);
        return;
    }

    const int row = blockIdx.x;
    const float* wr = W + (size_t)row * KDIM + tid * 16;

    float v[16];
    #pragma unroll
    for (int q = 0; q < 4; q++) {
        float4 t = *reinterpret_cast<const float4*>(wr + q * 4);
        v[q * 4 + 0] = t.x; v[q * 4 + 1] = t.y;
        v[q * 4 + 2] = t.z; v[q * 4 + 3] = t.w;
    }

    float a = 0.f;
    #pragma unroll
    for (int j = 0; j < 16; j++) a += v[j];
    #pragma unroll
    for (int o = 16; o; o >>= 1) a += __shfl_xor_sync(0xffffffffu, a, o);
    if ((tid & 31) == 0) sred[tid >> 5] = a;
    __syncthreads();
    if (tid == 0) {
        float t = 0.f;
        for (int j = 0; j < 8; j++) t += sred[j];
        sred[0] = t * (1.0f / KDIM);
    }
    __syncthreads();
    const float mu = sred[0];
    __syncthreads();

    float b = 0.f;
    #pragma unroll
    for (int j = 0; j < 16; j++) b += fabsf(v[j] - mu);
    #pragma unroll
    for (int o = 16; o; o >>= 1) b += __shfl_xor_sync(0xffffffffu, b, o);
    if ((tid & 31) == 0) sred[tid >> 5] = b;
    __syncthreads();
    if (tid == 0) {
        float t = 0.f;
        for (int j = 0; j < 8; j++) t += sred[j];
        sred[0] = t * (1.0f / KDIM);
    }
    __syncthreads();
    const float scale = sred[0];

    __half o16[16];
    #pragma unroll
    for (int w8 = 0; w8 < 2; w8++) {
        const float* vw = v + w8 * 8;
        int best = 0;
        float bv = fabsf(vw[0]);
        #pragma unroll
        for (int j = 1; j < 8; j++) {
            float av = fabsf(vw[j]);
            if (av > bv) { bv = av; best = j; }   // strict > == first argmax
        }
        #pragma unroll
        for (int j = 0; j < 8; j++) {
            float wc = vw[j] - mu;
            float q = (wc > 0.f) ? scale : ((wc < 0.f) ? -scale : 0.f);
            if (j == best) q = vw[j];
            o16[w8 * 8 + j] = __float2half_rn(q);
        }
    }
    __half* outr = g_wh + (size_t)row * KDIM + tid * 16;
    *reinterpret_cast<uint4*>(outr)     = *reinterpret_cast<const uint4*>(o16);
    *reinterpret_cast<uint4*>(outr + 8) = *reinterpret_cast<const uint4*>(o16 + 8);
}

// ---------------------------------------------------------- fp16 GEMM kernel
// out[m,n] = sum_k g_xh[m,k] * g_wh[n,k] + bias[n]
// 128x128 CTA tile, BK=64, 3-stage cp.async, 2 CTAs/SM, mma.sync.m16n8k16.
// Per-chunk body EXACT R14; main loop unrolled by 3 so the compute/load
// stage indices (and thus all smem stage addresses) are compile-time.
__global__ __launch_bounds__(256, 2) void gemm_kernel(const float* __restrict__ bias,
                                                      float* __restrict__ out) {
    extern __shared__ __align__(1024) char smem[];
    const uint32_t sbase = smem_u32(smem);
    const int tid = threadIdx.x;
    const int lane = tid & 31;
    const int wid = tid >> 5;
    const int wm = wid & 1;          // 2 warps along M (64 rows each)
    const int wn = wid >> 1;         // 4 warps along N (32 cols each)

    const int m0 = blockIdx.y * BM;
    const int n0 = blockIdx.x * BN;
    const __half* Xb = g_xh + (size_t)m0 * KDIM;
    const __half* Wb = g_wh + (size_t)n0 * KDIM;

    // ---- cp.async per-thread constants (16B = 8 halves per chunk) ----
    const int kb    = tid & 7;            // 16B chunk within 128B row
    const int rbase = tid >> 3;           // base row (+= 32 per iteration)
    const uint32_t dA0 = (uint32_t)rbase * 128 + (uint32_t)((kb ^ (rbase & 7)) << 4);
    const uint32_t dB0 = ASTAGE + dA0;
    const __half* srcA0 = Xb + (size_t)rbase * KDIM + kb * 8;
    const __half* srcB0 = Wb + (size_t)rbase * KDIM + kb * 8;

    // ---- ldmatrix per-lane constants ----
    const int e7 = lane & 7;
    const int tA = lane >> 4;             // A: k-chunk select bit
    const int tB = (lane >> 3) & 1;       // B: k-chunk select bit
    uint32_t aoff[4], boff[2];
    #pragma unroll
    for (int mt = 0; mt < 4; mt++) {
        // A 16x16 tile: lanes 0-15 -> rows 0-15 (k 0-7), lanes 16-31 -> k 8-15
        const int rowAf = wm * 64 + mt * 16 + (lane & 15);
        aoff[mt] = (uint32_t)rowAf * 128;
    }
    #pragma unroll
    for (int ntp = 0; ntp < 2; ntp++) {
        // B 16(n)x16(k) tile: lanes {0-7,8-15} -> n 0-7 (k 0-7, 8-15),
        //                     lanes {16-23,24-31} -> n 8-15
        const int rowBf = wn * 32 + ntp * 16 + e7 + ((lane >> 4) & 1) * 8;
        boff[ntp] = ASTAGE + (uint32_t)rowBf * 128;
    }

    float acc[4][4][4];
    #pragma unroll
    for (int mt = 0; mt < 4; mt++)
        #pragma unroll
        for (int nt = 0; nt < 4; nt++)
            #pragma unroll
            for (int q = 0; q < 4; q++) acc[mt][nt][q] = 0.f;

    // ---- prologue: fill STAGES-1 stages ----
    #pragma unroll
    for (int s = 0; s < STAGES - 1; s++) {
        const uint32_t stg = sbase + s * STG_BYTES;
        #pragma unroll
        for (int i = 0; i < 4; i++)
            cp16(stg + dA0 + i * 4096, srcA0 + (size_t)i * 32 * KDIM + s * BK);
        #pragma unroll
        for (int i = 0; i < 4; i++)
            cp16(stg + dB0 + i * 4096, srcB0 + (size_t)i * 32 * KDIM + s * BK);
        asm volatile("cp.async.commit_group;" ::: "memory");
    }

    // ---- one chunk, stage indices compile-time (body EXACT R14 order) ----
#define GEMM_CHUNK(c_, SC_, SL_)                                               \
    {                                                                          \
        asm volatile("cp.async.wait_group %0;" :: "n"(STAGES - 2) : "memory"); \
        __syncthreads();                                                       \
        const int cn_ = (c_) + STAGES - 1;                                     \
        if (cn_ < KCH) {                                                       \
            const uint32_t stgl_ = sbase + (SL_) * STG_BYTES;                  \
            _Pragma("unroll")                                                  \
            for (int i = 0; i < 4; i++)                                        \
                cp16(stgl_ + dA0 + i * 4096,                                   \
                     srcA0 + (size_t)i * 32 * KDIM + cn_ * BK);                \
            _Pragma("unroll")                                                  \
            for (int i = 0; i < 4; i++)                                        \
                cp16(stgl_ + dB0 + i * 4096,                                   \
                     srcB0 + (size_t)i * 32 * KDIM + cn_ * BK);                \
        }                                                                      \
        asm volatile("cp.async.commit_group;" ::: "memory");                   \
        const uint32_t stg_ = sbase + (SC_) * STG_BYTES;                       \
        _Pragma("unroll")                                                      \
        for (int ks = 0; ks < 4; ks++) {                                       \
            uint32_t af[4][4], bf[2][4];                                       \
            const uint32_t cA = (uint32_t)((((ks << 1) + tA) ^ e7) << 4);      \
            const uint32_t cB = (uint32_t)((((ks << 1) + tB) ^ e7) << 4);      \
            _Pragma("unroll")                                                  \
            for (int mt = 0; mt < 4; mt++) ldsm4(af[mt], stg_ + aoff[mt] + cA);\
            _Pragma("unroll")                                                  \
            for (int ntp = 0; ntp < 2; ntp++)                                  \
                ldsm4(bf[ntp], stg_ + boff[ntp] + cB);                         \
            _Pragma("unroll")                                                  \
            for (int mt = 0; mt < 4; mt++)                                     \
                _Pragma("unroll")                                              \
                for (int ntp = 0; ntp < 2; ntp++) {                            \
                    mma_f16(acc[mt][ntp * 2 + 0], af[mt], &bf[ntp][0]);        \
                    mma_f16(acc[mt][ntp * 2 + 1], af[mt], &bf[ntp][2]);        \
                }                                                              \
        }                                                                      \
    }

    // ---- main loop: 21 x 3 chunks + 1 tail; stage pattern period 3 ----
    for (int c = 0; c < KCH - 1; c += 3) {
        GEMM_CHUNK(c,     0, 2);
        GEMM_CHUNK(c + 1, 1, 0);
        GEMM_CHUNK(c + 2, 2, 1);
    }
    GEMM_CHUNK(KCH - 1, 0, 2);     // chunk 63: 63 % 3 == 0
#undef GEMM_CHUNK

    // ---- epilogue: bias add + store ----
    const int g = lane >> 2;
    const int tg = lane & 3;
    float2 bv[4];
    #pragma unroll
    for (int nt = 0; nt < 4; nt++)
        bv[nt] = *reinterpret_cast<const float2*>(bias + n0 + wn * 32 + nt * 8 + tg * 2);

    #pragma unroll
    for (int mt = 0; mt < 4; mt++) {
        const int row = m0 + wm * 64 + mt * 16 + g;
        float* o0 = out + (size_t)row * NDIM + n0 + wn * 32;
        float* o1 = o0 + 8 * NDIM;   // row + 8
        #pragma unroll
        for (int nt = 0; nt < 4; nt++) {
            const int col = nt * 8 + tg * 2;
            float2 v0, v1;
            v0.x = acc[mt][nt][0] + bv[nt].x;
            v0.y = acc[mt][nt][1] + bv[nt].y;
            v1.x = acc[mt][nt][2] + bv[nt].x;
            v1.y = acc[mt][nt][3] + bv[nt].y;
            *reinterpret_cast<float2*>(o0 + col) = v0;
            *reinterpret_cast<float2*>(o1 + col) = v1;
        }
    }
}

// ------------------------------------------------------------------ launch
extern "C" void kernel_launch(void* const* d_in, const int* in_sizes, int n_in,
                              void* d_out, int out_size) {
    (void)in_sizes; (void)n_in; (void)out_size;
    const float* X = (const float*)d_in[0];     // [4,2048,4096] -> [8192,4096]
    const float* W = (const float*)d_in[1];     // [4096,4096]
    const float* B = (const float*)d_in[2];     // [4096]
    float* O = (float*)d_out;                   // [8192,4096]

    const int conv_blocks = (MDIM * KDIM / 8) / 256;          // 16384
    prep_all_kernel<<<NDIM + conv_blocks, 256>>>(W, X);       // fused pre-pass

    cudaFuncSetAttribute(gemm_kernel, cudaFuncAttributeMaxDynamicSharedMemorySize, SMEM_BYTES);
    dim3 grid(NDIM / BN, MDIM / BM);            // (32, 64)
    gemm_kernel<<<grid, 256, SMEM_BYTES>>>(B, O);
}